// round 11
// baseline (speedup 1.0000x reference)
#include <cuda_runtime.h>
#include <cuda_bf16.h>
#include <math.h>
#include <stdint.h>

// Problem dims (fixed by the dataset)
#define BB 4
#define LL 4096
#define DD 1024
#define NN 64
#define MM (BB * LL)
#define NCH 128
#define TCH (LL / NCH)    // 32

typedef unsigned int u32;
typedef __nv_bfloat16 bf16;

// ---------------- scratch (device globals: no allocation allowed) ----------------
__device__ bf16 g_WpH[DD * 2 * NN], g_WpL[DD * 2 * NN];   // [1024][128]
__device__ bf16 g_WsH[DD * NN],     g_WsL[DD * NN];       // [1024][64]
__device__ bf16 g_WoH[NN * DD],     g_WoL[NN * DD];       // [64][1024]
__device__ float g_P [MM * NN];                            // dt * Bt * u
__device__ float g_Ct[MM * NN];
__device__ bf16  g_yH[MM * NN], g_yL[MM * NN];            // [16384][64]
__device__ float g_carryT[BB * NN * NCH];                 // transposed partials
__device__ float g_ebias[3 * NN];
__device__ float g_sd[3 * NN];                            // dt | decay | decay^TCH

// ---------------- helpers ----------------
#define SW128(o) ((u32)(o) ^ ((((u32)(o)) >> 3) & 0x70))

__device__ __forceinline__ u32 s2u(const void* p) {
    u32 a;
    asm("{ .reg .u64 t; cvta.to.shared.u64 t, %1; cvt.u32.u64 %0, t; }" : "=r"(a) : "l"(p));
    return a;
}
__device__ __forceinline__ float sp(float v) { return v > 20.f ? v : log1pf(expf(v)); }

#define LDSM4(r, a)                                                                    \
    asm volatile("ldmatrix.sync.aligned.m8n8.x4.shared.b16 {%0,%1,%2,%3}, [%4];"      \
                 : "=r"((r)[0]), "=r"((r)[1]), "=r"((r)[2]), "=r"((r)[3]) : "r"(a))
#define LDSM2T(r, a)                                                                   \
    asm volatile("ldmatrix.sync.aligned.m8n8.x2.trans.shared.b16 {%0,%1}, [%2];"      \
                 : "=r"((r)[0]), "=r"((r)[1]) : "r"(a))
#define MMA(d, a, b)                                                                   \
    asm volatile("mma.sync.aligned.m16n8k16.row.col.f32.bf16.bf16.f32 "               \
                 "{%0,%1,%2,%3}, {%4,%5,%6,%7}, {%8,%9}, {%0,%1,%2,%3};"              \
                 : "+f"((d)[0]), "+f"((d)[1]), "+f"((d)[2]), "+f"((d)[3])             \
                 : "r"((a)[0]), "r"((a)[1]), "r"((a)[2]), "r"((a)[3]),                \
                   "r"((b)[0]), "r"((b)[1]))

#define CPA16(sa, gp)                                                                  \
    asm volatile("cp.async.cg.shared.global [%0], [%1], 16;" :: "r"((u32)(sa)), "l"(gp))
#define CPA_COMMIT() asm volatile("cp.async.commit_group;" ::: "memory")
#define CPA_WAIT1()  asm volatile("cp.async.wait_group 1;" ::: "memory")
#define CPA_WAIT0()  asm volatile("cp.async.wait_group 0;" ::: "memory")

__device__ __forceinline__ void split1(float v, bf16& h, bf16& l) {
    h = __float2bfloat16(v);
    l = __float2bfloat16(v - __bfloat162float(h));
}
__device__ __forceinline__ void split_store8(char* hiP, char* loP, float4 v) {
    bf16 h0, l0, h1, l1, h2, l2, h3, l3;
    split1(v.x, h0, l0); split1(v.y, h1, l1);
    split1(v.z, h2, l2); split1(v.w, h3, l3);
    __nv_bfloat162 hp0 = {h0, h1}, hp1 = {h2, h3};
    __nv_bfloat162 lp0 = {l0, l1}, lp1 = {l2, l3};
    *(uint2*)hiP = make_uint2(*(u32*)&hp0, *(u32*)&hp1);
    *(uint2*)loP = make_uint2(*(u32*)&lp0, *(u32*)&lp1);
}
__device__ __forceinline__ float4 f4fma(float4 acc, float4 a, float4 b) {
    acc.x = fmaf(a.x, b.x, acc.x); acc.y = fmaf(a.y, b.y, acc.y);
    acc.z = fmaf(a.z, b.z, acc.z); acc.w = fmaf(a.w, b.w, acc.w);
    return acc;
}

// ---------------- kernel 0: weight bf16 hi/lo split + ebias + scan consts --------
__global__ void __launch_bounds__(256) prep_kernel(
    const float* __restrict__ Wp, const float* __restrict__ Ws,
    const float* __restrict__ Wo, const float* __restrict__ cb,
    const float* __restrict__ bp, const float* __restrict__ bs,
    const float* __restrict__ A_log, const float* __restrict__ dt_log,
    float* __restrict__ ebias, float* __restrict__ sd)
{
    const int gtid = blockIdx.x * 256 + threadIdx.x;
    const int NT = gridDim.x * 256;

    for (int i = gtid; i < DD * 2 * NN; i += NT) split1(Wp[i], g_WpH[i], g_WpL[i]);
    for (int i = gtid; i < DD * NN;     i += NT) split1(Ws[i], g_WsH[i], g_WsL[i]);
    for (int i = gtid; i < NN * DD;     i += NT) split1(Wo[i], g_WoH[i], g_WoL[i]);

    if (gtid < 2 * NN) {
        float s = bp[gtid];
#pragma unroll 8
        for (int d = 0; d < DD; ++d) s = fmaf(cb[d], Wp[(size_t)d * 2 * NN + gtid], s);
        ebias[gtid] = s;
    } else if (gtid < 3 * NN) {
        ebias[gtid] = bs[gtid - 2 * NN];
    } else if (gtid < 3 * NN + NN) {
        int n = gtid - 3 * NN;
        float dt = sp(dt_log[n]);
        float decay = 1.f - dt * sp(A_log[n]);
        float dp = decay;
#pragma unroll
        for (int i = 0; i < 5; ++i) dp *= dp;      // decay^32
        sd[n] = dt;
        sd[NN + n] = decay;
        sd[2 * NN + n] = dp;
    }
}

// ---------------- kernel 1: fused conv + gates + u, emits P = dt*Bt*u and Ct -----
#define FX(b)   (0      + (b) * 17408)   // raw x: 67 rows x 256B
#define FBPH(b) (34816  + (b) * 16384)   // Wp hi: 64x128 bf16, 2 panels SW128
#define FBPL(b) (67584  + (b) * 16384)
#define FBSH(b) (100352 + (b) * 8192)    // Ws hi: 64x64 bf16 SW128
#define FBSL(b) (116736 + (b) * 8192)
#define FACH(b) (133120 + (b) * 8192)    // conv split hi
#define FACL(b) (149504 + (b) * 8192)
#define FAXH(b) (165888 + (b) * 8192)    // x split hi
#define FAXL(b) (182272 + (b) * 8192)
#define FUSED_SMEM 198656
#define USTRIDE 66                       // u exchange row stride (floats)

__global__ void __launch_bounds__(384, 1) tc_fused(
    const float* __restrict__ x, const float* __restrict__ cw,
    const float* __restrict__ ebias, const float* __restrict__ sd)
{
    extern __shared__ char dsm[];
    const int tid = threadIdx.x;
    const int lane = tid & 31, w = tid >> 5;
    const int m0 = blockIdx.x * 64;
    const bool seqstart = ((m0 & (LL - 1)) == 0);

    const bool is_gate = (w < 8);
    const int mw = is_gate ? ((w >> 2) * 32) : (((w - 8) >> 1) * 32);
    const int nw = is_gate ? ((w & 3) * 32) : (((w - 8) & 1) * 32);

    float acc[2][4][4];
#pragma unroll
    for (int mt = 0; mt < 2; ++mt)
#pragma unroll
        for (int nt = 0; nt < 4; ++nt)
#pragma unroll
            for (int q = 0; q < 4; ++q) acc[mt][nt][q] = 0.f;

    const int arow = lane & 15, acol = (lane >> 4) * 8;
    const int brow = lane & 15;

    const u32 sbase = s2u(dsm);

    auto stage = [&](int kt, int buf) {
        for (int i = tid; i < 67 * 16; i += 384) {
            int rr = i >> 4, ch = i & 15;
            u32 dst = sbase + FX(buf) + rr * 256 + ch * 16;
            if (seqstart && rr < 3) {
                *(uint4*)(dsm + FX(buf) + rr * 256 + ch * 16) = make_uint4(0, 0, 0, 0);
            } else {
                CPA16(dst, x + (size_t)(m0 - 3 + rr) * DD + kt * 64 + ch * 4);
            }
        }
        for (int i = tid; i < 64 * 16; i += 384) {
            int r = i >> 4, ch = i & 15;
            size_t gb = (size_t)(kt * 64 + r) * 256 + ch * 16;
            u32 sw = (u32)(ch >> 3) * 8192 + SW128(r * 128 + (ch & 7) * 16);
            CPA16(sbase + FBPH(buf) + sw, (const char*)g_WpH + gb);
            CPA16(sbase + FBPL(buf) + sw, (const char*)g_WpL + gb);
        }
        for (int i = tid; i < 64 * 8; i += 384) {
            int r = i >> 3, ch = i & 7;
            size_t gb = (size_t)(kt * 64 + r) * 128 + ch * 16;
            u32 sw = SW128(r * 128 + ch * 16);
            CPA16(sbase + FBSH(buf) + sw, (const char*)g_WsH + gb);
            CPA16(sbase + FBSL(buf) + sw, (const char*)g_WsL + gb);
        }
    };

    stage(0, 0);
    CPA_COMMIT();

    for (int kt = 0; kt < DD / 64; ++kt) {
        const int buf = kt & 1;
        if (kt + 1 < DD / 64) {
            stage(kt + 1, buf ^ 1);
            CPA_COMMIT();
            CPA_WAIT1();
        } else {
            CPA_WAIT0();
        }
        __syncthreads();

        // ---- conv + split -> sAc(buf); raw x split -> sAx(buf) ----
        char* sX = dsm + FX(buf);
#pragma unroll
        for (int i = tid; i < 64 * 16; i += 384) {
            int r = i >> 4, ch = i & 15;
            float4 xm3 = *(const float4*)(sX + (r + 0) * 256 + ch * 16);
            float4 xm2 = *(const float4*)(sX + (r + 1) * 256 + ch * 16);
            float4 xm1 = *(const float4*)(sX + (r + 2) * 256 + ch * 16);
            float4 xc  = *(const float4*)(sX + (r + 3) * 256 + ch * 16);
            int dcol = kt * 64 + ch * 4;
            float4 w0 = *(const float4*)(cw + 0 * DD + dcol);
            float4 w1 = *(const float4*)(cw + 1 * DD + dcol);
            float4 w2 = *(const float4*)(cw + 2 * DD + dcol);
            float4 w3 = *(const float4*)(cw + 3 * DD + dcol);
            float4 o = make_float4(0.f, 0.f, 0.f, 0.f);
            o = f4fma(o, w0, xm3); o = f4fma(o, w1, xm2);
            o = f4fma(o, w2, xm1); o = f4fma(o, w3, xc);
            u32 sw = SW128(r * 128 + ch * 8);
            split_store8(dsm + FACH(buf) + sw, dsm + FACL(buf) + sw, o);
            split_store8(dsm + FAXH(buf) + sw, dsm + FAXL(buf) + sw, xc);
        }
        __syncthreads();

        // ---- MMA ----
        const u32 aH = sbase + (is_gate ? FACH(buf) : FAXH(buf));
        const u32 aL = sbase + (is_gate ? FACL(buf) : FAXL(buf));
        const u32 bH = sbase + (is_gate ? FBPH(buf) : FBSH(buf));
        const u32 bL = sbase + (is_gate ? FBPL(buf) : FBSL(buf));
#pragma unroll
        for (int ks = 0; ks < 4; ++ks) {
            u32 ah[2][4], al[2][4], bh[4][2], bl[4][2];
#pragma unroll
            for (int mt = 0; mt < 2; ++mt) {
                u32 off = SW128((mw + mt * 16 + arow) * 128 + (ks * 16 + acol) * 2);
                LDSM4(ah[mt], aH + off);
                LDSM4(al[mt], aL + off);
            }
#pragma unroll
            for (int nt = 0; nt < 4; ++nt) {
                int col = nw + nt * 8;
                u32 off = (u32)(col >> 6) * 8192 +
                          SW128((ks * 16 + brow) * 128 + (col & 63) * 2);
                LDSM2T(bh[nt], bH + off);
                LDSM2T(bl[nt], bL + off);
            }
#pragma unroll
            for (int mt = 0; mt < 2; ++mt)
#pragma unroll
                for (int nt = 0; nt < 4; ++nt) {
                    MMA(acc[mt][nt], ah[mt], bh[nt]);
                    MMA(acc[mt][nt], ah[mt], bl[nt]);
                    MMA(acc[mt][nt], al[mt], bh[nt]);
                }
        }
        // REQUIRED: next iteration's stage() overwrites buffers read above.
        __syncthreads();
    }

    // ---- epilogue: u warps -> smem exchange; gate warps -> P and Ct ----
    float* sU = (float*)dsm;   // 64 x USTRIDE floats (reuses FX region, post-barrier)
    if (!is_gate) {
#pragma unroll
        for (int mt = 0; mt < 2; ++mt)
#pragma unroll
            for (int nt = 0; nt < 4; ++nt) {
                int r = mw + mt * 16 + (lane >> 2);
                int col = nw + nt * 8 + 2 * (lane & 3);
                float b0v = ebias[2 * NN + col], b1v = ebias[2 * NN + col + 1];
                sU[r * USTRIDE + col]           = acc[mt][nt][0] + b0v;
                sU[r * USTRIDE + col + 1]       = acc[mt][nt][1] + b1v;
                sU[(r + 8) * USTRIDE + col]     = acc[mt][nt][2] + b0v;
                sU[(r + 8) * USTRIDE + col + 1] = acc[mt][nt][3] + b1v;
            }
    }
    __syncthreads();
    if (is_gate) {
#pragma unroll
        for (int mt = 0; mt < 2; ++mt)
#pragma unroll
            for (int nt = 0; nt < 4; ++nt) {
                int r = mw + mt * 16 + (lane >> 2);
                int col = nw + nt * 8 + 2 * (lane & 3);
                float b0v = ebias[col], b1v = ebias[col + 1];
                float vx = acc[mt][nt][0] + b0v, vy = acc[mt][nt][1] + b1v;
                float vz = acc[mt][nt][2] + b0v, vw = acc[mt][nt][3] + b1v;
                if (col < 64) {
                    float dt0 = sd[col], dt1 = sd[col + 1];
                    float p0 = dt0 * sp(vx) * sU[r * USTRIDE + col];
                    float p1 = dt1 * sp(vy) * sU[r * USTRIDE + col + 1];
                    float p2 = dt0 * sp(vz) * sU[(r + 8) * USTRIDE + col];
                    float p3 = dt1 * sp(vw) * sU[(r + 8) * USTRIDE + col + 1];
                    *(float2*)&g_P[(size_t)(m0 + r) * NN + col] = make_float2(p0, p1);
                    *(float2*)&g_P[(size_t)(m0 + r + 8) * NN + col] = make_float2(p2, p3);
                } else {
                    vx = tanhf(vx); vy = tanhf(vy); vz = tanhf(vz); vw = tanhf(vw);
                    *(float2*)&g_Ct[(size_t)(m0 + r) * NN + col - 64] = make_float2(vx, vy);
                    *(float2*)&g_Ct[(size_t)(m0 + r + 8) * NN + col - 64] = make_float2(vz, vw);
                }
            }
    }
}

// ---------------- kernel 2: out = y @ Wo + bo ----------------
// grid (MM/256, DD/128): B (Wo panel) staged ONCE, 4 M-tiles per block with
// double-buffered cp.async A staging.
#define OAH(b) (0     + (b) * 8192)
#define OAL(b) (16384 + (b) * 8192)
#define OBH    32768
#define OBL    49152
#define TCOUT_SMEM 65536

__global__ void __launch_bounds__(256) tc_out(
    const float* __restrict__ bo, float* __restrict__ out)
{
    extern __shared__ char dsm[];
    const int tid = threadIdx.x;
    const int lane = tid & 31, w = tid >> 5;
    const int mw = (w >> 2) * 32, nw = (w & 3) * 32;
    const int mbase = blockIdx.x * 256;
    const int n0 = blockIdx.y * 128;

    const u32 sbase = s2u(dsm);
    const int arow = lane & 15, acol = (lane >> 4) * 8;
    const int brow = lane & 15;

    auto stageA = [&](int mi, int buf) {
#pragma unroll
        for (int i = tid; i < 64 * 8; i += 256) {
            int r = i >> 3, ch = i & 7;
            size_t gb = (size_t)(mbase + mi * 64 + r) * 128 + ch * 16;
            u32 sw = SW128(r * 128 + ch * 16);
            CPA16(sbase + OAH(buf) + sw, (const char*)g_yH + gb);
            CPA16(sbase + OAL(buf) + sw, (const char*)g_yL + gb);
        }
    };

    // stage B panel (once) + A(0) in group 0
#pragma unroll
    for (int i = tid; i < 64 * 16; i += 256) {
        int r = i >> 4, ch = i & 15;
        size_t gb = (size_t)r * 2048 + (size_t)n0 * 2 + ch * 16;
        u32 sw = (u32)(ch >> 3) * 8192 + SW128(r * 128 + (ch & 7) * 16);
        CPA16(sbase + OBH + sw, (const char*)g_WoH + gb);
        CPA16(sbase + OBL + sw, (const char*)g_WoL + gb);
    }
    stageA(0, 0);
    CPA_COMMIT();

    for (int mi = 0; mi < 4; ++mi) {
        const int buf = mi & 1;
        if (mi + 1 < 4) {
            stageA(mi + 1, buf ^ 1);
            CPA_COMMIT();
            CPA_WAIT1();
        } else {
            CPA_WAIT0();
        }
        __syncthreads();

        float acc[2][4][4];
#pragma unroll
        for (int mt = 0; mt < 2; ++mt)
#pragma unroll
            for (int nt = 0; nt < 4; ++nt)
#pragma unroll
                for (int q = 0; q < 4; ++q) acc[mt][nt][q] = 0.f;

        const u32 aAh = sbase + OAH(buf), aAl = sbase + OAL(buf);
#pragma unroll
        for (int ks = 0; ks < 4; ++ks) {
            u32 ah[2][4], al[2][4], bh[4][2], bl[4][2];
#pragma unroll
            for (int mt = 0; mt < 2; ++mt) {
                u32 off = SW128((mw + mt * 16 + arow) * 128 + (ks * 16 + acol) * 2);
                LDSM4(ah[mt], aAh + off);
                LDSM4(al[mt], aAl + off);
            }
#pragma unroll
            for (int nt = 0; nt < 4; ++nt) {
                int col = nw + nt * 8;
                u32 off = (u32)(col >> 6) * 8192 +
                          SW128((ks * 16 + brow) * 128 + (col & 63) * 2);
                LDSM2T(bh[nt], sbase + OBH + off);
                LDSM2T(bl[nt], sbase + OBL + off);
            }
#pragma unroll
            for (int mt = 0; mt < 2; ++mt)
#pragma unroll
                for (int nt = 0; nt < 4; ++nt) {
                    MMA(acc[mt][nt], ah[mt], bh[nt]);
                    MMA(acc[mt][nt], ah[mt], bl[nt]);
                    MMA(acc[mt][nt], al[mt], bh[nt]);
                }
        }

#pragma unroll
        for (int mt = 0; mt < 2; ++mt)
#pragma unroll
            for (int nt = 0; nt < 4; ++nt) {
                int r0 = mbase + mi * 64 + mw + mt * 16 + (lane >> 2);
                int col = n0 + nw + nt * 8 + 2 * (lane & 3);
                float b0v = bo[col], b1v = bo[col + 1];
                *(float2*)&out[(size_t)r0 * DD + col] =
                    make_float2(acc[mt][nt][0] + b0v, acc[mt][nt][1] + b1v);
                *(float2*)&out[(size_t)(r0 + 8) * DD + col] =
                    make_float2(acc[mt][nt][2] + b0v, acc[mt][nt][3] + b1v);
            }
        // next iteration's stageA overwrites buf^1 (read in iteration mi-1);
        // barrier ensures all readers finished.
        __syncthreads();
    }
}

// ---------------- scan kernels (chunk-parallel linear recurrence) ----------------
__global__ void __launch_bounds__(256) scan_partial(
    const float* __restrict__ P, const float* __restrict__ sd,
    float* __restrict__ carryT)
{
    const int n = threadIdx.x & 63;
    const int ch = blockIdx.x * 4 + (threadIdx.x >> 6);
    const int b = blockIdx.y;
    const float decay = sd[NN + n];
    const float* p = P + ((size_t)b * LL + (size_t)ch * TCH) * NN + n;
    float s = 0.f;
#pragma unroll
    for (int t = 0; t < TCH; ++t) s = fmaf(decay, s, p[(size_t)t * NN]);
    carryT[((size_t)b * NN + n) * NCH + ch] = s;
}

// scan_final computes its own carry-in from the partials row (L2-resident),
// then runs the local scan and emits y hi/lo.
__global__ void __launch_bounds__(256) scan_final(
    const float* __restrict__ P, const float* __restrict__ Ct,
    const float* __restrict__ sd, const float* __restrict__ carryT)
{
    const int n = threadIdx.x & 63;
    const int ch = blockIdx.x * 4 + (threadIdx.x >> 6);
    const int b = blockIdx.y;
    const float decay = sd[NN + n];
    const float dp = sd[2 * NN + n];

    // carry-in: c = sum_{j<ch} dp^(ch-1-j) * e_j
    const float* erow = carryT + ((size_t)b * NN + n) * NCH;
    float s = 0.f;
#pragma unroll 4
    for (int j = 0; j < ch; ++j) s = fmaf(dp, s, erow[j]);

    size_t base = ((size_t)b * LL + (size_t)ch * TCH) * NN + n;
#pragma unroll
    for (int t = 0; t < TCH; ++t) {
        size_t idx = base + (size_t)t * NN;
        s = fmaf(decay, s, P[idx]);
        float yv = Ct[idx] * s;
        split1(yv, g_yH[idx], g_yL[idx]);
    }
}

// ---------------- launch ----------------
extern "C" void kernel_launch(void* const* d_in, const int* in_sizes, int n_in,
                              void* d_out, int out_size)
{
    const float* x      = (const float*)d_in[0];
    const float* conv_w = (const float*)d_in[1];
    const float* conv_b = (const float*)d_in[2];
    const float* Wp     = (const float*)d_in[3];
    const float* bp     = (const float*)d_in[4];
    const float* Ws     = (const float*)d_in[5];
    const float* bs     = (const float*)d_in[6];
    const float* A_log  = (const float*)d_in[7];
    const float* dt_log = (const float*)d_in[8];
    const float* Wo     = (const float*)d_in[9];
    const float* bo     = (const float*)d_in[10];
    float* out = (float*)d_out;

    float *p_p, *ct_p, *carry_p, *ebias_p, *sd_p;
    cudaGetSymbolAddress((void**)&p_p,     g_P);
    cudaGetSymbolAddress((void**)&ct_p,    g_Ct);
    cudaGetSymbolAddress((void**)&carry_p, g_carryT);
    cudaGetSymbolAddress((void**)&ebias_p, g_ebias);
    cudaGetSymbolAddress((void**)&sd_p,    g_sd);

    static int attr_done = 0;
    if (!attr_done) {
        cudaFuncSetAttribute(tc_fused, cudaFuncAttributeMaxDynamicSharedMemorySize, FUSED_SMEM);
        cudaFuncSetAttribute(tc_out, cudaFuncAttributeMaxDynamicSharedMemorySize, TCOUT_SMEM);
        attr_done = 1;
    }

    // 0) weights -> bf16 hi/lo, effective biases, scan constants
    prep_kernel<<<64, 256>>>(Wp, Ws, Wo, conv_b, bp, bs, A_log, dt_log, ebias_p, sd_p);

    // 1) fused conv + gate GEMM + u GEMM -> P (= dt*Bt*u) and Ct
    tc_fused<<<MM / 64, 384, FUSED_SMEM>>>(x, conv_w, ebias_p, sd_p);

    // 2) chunk-parallel scan -> y (bf16 hi/lo), carry-in computed per thread
    scan_partial<<<dim3(NCH / 4, BB), 256>>>(p_p, sd_p, carry_p);
    scan_final<<<dim3(NCH / 4, BB), 256>>>(p_p, ct_p, sd_p, carry_p);

    // 3) out = y @ Wo + bo  (B panel reused across 4 M-tiles per block)
    tc_out<<<dim3(MM / 256, DD / 128), 256, TCOUT_SMEM>>>(bo, out);
}

// round 12
// speedup vs baseline: 1.1096x; 1.1096x over previous
#include <cuda_runtime.h>
#include <cuda_bf16.h>
#include <math.h>
#include <stdint.h>

// Problem dims (fixed by the dataset)
#define BB 4
#define LL 4096
#define DD 1024
#define NN 64
#define MM (BB * LL)
#define NCH 128
#define TCH (LL / NCH)    // 32

typedef unsigned int u32;
typedef __nv_bfloat16 bf16;

// ---------------- scratch (device globals: no allocation allowed) ----------------
__device__ bf16 g_WpH[DD * 2 * NN], g_WpL[DD * 2 * NN];   // [1024][128]
__device__ bf16 g_WsH[DD * NN],     g_WsL[DD * NN];       // [1024][64]
__device__ bf16 g_WoH[NN * DD],     g_WoL[NN * DD];       // [64][1024]
__device__ float g_P [MM * NN];                            // dt * Bt * u
__device__ float g_Ct[MM * NN];
__device__ bf16  g_yH[MM * NN], g_yL[MM * NN];            // [16384][64]
__device__ float g_carryT[BB * NN * NCH];                 // transposed partials
__device__ float g_ebias[3 * NN];
__device__ float g_sd[3 * NN];                            // dt | decay | decay^TCH

// ---------------- helpers ----------------
#define SW128(o) ((u32)(o) ^ ((((u32)(o)) >> 3) & 0x70))

__device__ __forceinline__ u32 s2u(const void* p) {
    u32 a;
    asm("{ .reg .u64 t; cvta.to.shared.u64 t, %1; cvt.u32.u64 %0, t; }" : "=r"(a) : "l"(p));
    return a;
}
__device__ __forceinline__ float sp(float v) { return v > 20.f ? v : log1pf(expf(v)); }

#define LDSM4(r, a)                                                                    \
    asm volatile("ldmatrix.sync.aligned.m8n8.x4.shared.b16 {%0,%1,%2,%3}, [%4];"      \
                 : "=r"((r)[0]), "=r"((r)[1]), "=r"((r)[2]), "=r"((r)[3]) : "r"(a))
#define LDSM2T(r, a)                                                                   \
    asm volatile("ldmatrix.sync.aligned.m8n8.x2.trans.shared.b16 {%0,%1}, [%2];"      \
                 : "=r"((r)[0]), "=r"((r)[1]) : "r"(a))
#define MMA(d, a, b)                                                                   \
    asm volatile("mma.sync.aligned.m16n8k16.row.col.f32.bf16.bf16.f32 "               \
                 "{%0,%1,%2,%3}, {%4,%5,%6,%7}, {%8,%9}, {%0,%1,%2,%3};"              \
                 : "+f"((d)[0]), "+f"((d)[1]), "+f"((d)[2]), "+f"((d)[3])             \
                 : "r"((a)[0]), "r"((a)[1]), "r"((a)[2]), "r"((a)[3]),                \
                   "r"((b)[0]), "r"((b)[1]))

#define CPA16(sa, gp)                                                                  \
    asm volatile("cp.async.cg.shared.global [%0], [%1], 16;" :: "r"((u32)(sa)), "l"(gp))
#define CPA_COMMIT() asm volatile("cp.async.commit_group;" ::: "memory")
#define CPA_WAIT1()  asm volatile("cp.async.wait_group 1;" ::: "memory")
#define CPA_WAIT0()  asm volatile("cp.async.wait_group 0;" ::: "memory")

__device__ __forceinline__ void split1(float v, bf16& h, bf16& l) {
    h = __float2bfloat16(v);
    l = __float2bfloat16(v - __bfloat162float(h));
}
__device__ __forceinline__ void split_store8(char* hiP, char* loP, float4 v) {
    bf16 h0, l0, h1, l1, h2, l2, h3, l3;
    split1(v.x, h0, l0); split1(v.y, h1, l1);
    split1(v.z, h2, l2); split1(v.w, h3, l3);
    __nv_bfloat162 hp0 = {h0, h1}, hp1 = {h2, h3};
    __nv_bfloat162 lp0 = {l0, l1}, lp1 = {l2, l3};
    *(uint2*)hiP = make_uint2(*(u32*)&hp0, *(u32*)&hp1);
    *(uint2*)loP = make_uint2(*(u32*)&lp0, *(u32*)&lp1);
}
__device__ __forceinline__ float4 f4fma(float4 acc, float4 a, float4 b) {
    acc.x = fmaf(a.x, b.x, acc.x); acc.y = fmaf(a.y, b.y, acc.y);
    acc.z = fmaf(a.z, b.z, acc.z); acc.w = fmaf(a.w, b.w, acc.w);
    return acc;
}

// ---------------- kernel 0: weight bf16 hi/lo split + ebias + scan consts --------
__global__ void __launch_bounds__(256) prep_kernel(
    const float* __restrict__ Wp, const float* __restrict__ Ws,
    const float* __restrict__ Wo, const float* __restrict__ cb,
    const float* __restrict__ bp, const float* __restrict__ bs,
    const float* __restrict__ A_log, const float* __restrict__ dt_log,
    float* __restrict__ ebias, float* __restrict__ sd)
{
    const int gtid = blockIdx.x * 256 + threadIdx.x;
    const int NT = gridDim.x * 256;

    for (int i = gtid; i < DD * 2 * NN; i += NT) split1(Wp[i], g_WpH[i], g_WpL[i]);
    for (int i = gtid; i < DD * NN;     i += NT) split1(Ws[i], g_WsH[i], g_WsL[i]);
    for (int i = gtid; i < NN * DD;     i += NT) split1(Wo[i], g_WoH[i], g_WoL[i]);

    if (gtid < 2 * NN) {
        float s = bp[gtid];
#pragma unroll 8
        for (int d = 0; d < DD; ++d) s = fmaf(cb[d], Wp[(size_t)d * 2 * NN + gtid], s);
        ebias[gtid] = s;
    } else if (gtid < 3 * NN) {
        ebias[gtid] = bs[gtid - 2 * NN];
    } else if (gtid < 3 * NN + NN) {
        int n = gtid - 3 * NN;
        float dt = sp(dt_log[n]);
        float decay = 1.f - dt * sp(A_log[n]);
        float dp = decay;
#pragma unroll
        for (int i = 0; i < 5; ++i) dp *= dp;      // decay^32
        sd[n] = dt;
        sd[NN + n] = decay;
        sd[2 * NN + n] = dp;
    }
}

// ---------------- kernel 1: fused conv + gates + u, emits P = dt*Bt*u and Ct -----
#define FX(b)   (0      + (b) * 17408)   // raw x: 67 rows x 256B
#define FBPH(b) (34816  + (b) * 16384)   // Wp hi: 64x128 bf16, 2 panels SW128
#define FBPL(b) (67584  + (b) * 16384)
#define FBSH(b) (100352 + (b) * 8192)    // Ws hi: 64x64 bf16 SW128
#define FBSL(b) (116736 + (b) * 8192)
#define FACH(b) (133120 + (b) * 8192)    // conv split hi
#define FACL(b) (149504 + (b) * 8192)
#define FAXH(b) (165888 + (b) * 8192)    // x split hi
#define FAXL(b) (182272 + (b) * 8192)
#define FUSED_SMEM 198656
#define USTRIDE 66                       // u exchange row stride (floats)

__global__ void __launch_bounds__(384, 1) tc_fused(
    const float* __restrict__ x, const float* __restrict__ cw,
    const float* __restrict__ ebias, const float* __restrict__ sd)
{
    extern __shared__ char dsm[];
    const int tid = threadIdx.x;
    const int lane = tid & 31, w = tid >> 5;
    const int m0 = blockIdx.x * 64;
    const bool seqstart = ((m0 & (LL - 1)) == 0);

    const bool is_gate = (w < 8);
    const int mw = is_gate ? ((w >> 2) * 32) : (((w - 8) >> 1) * 32);
    const int nw = is_gate ? ((w & 3) * 32) : (((w - 8) & 1) * 32);

    float acc[2][4][4];
#pragma unroll
    for (int mt = 0; mt < 2; ++mt)
#pragma unroll
        for (int nt = 0; nt < 4; ++nt)
#pragma unroll
            for (int q = 0; q < 4; ++q) acc[mt][nt][q] = 0.f;

    const int arow = lane & 15, acol = (lane >> 4) * 8;
    const int brow = lane & 15;

    const u32 sbase = s2u(dsm);

    auto stage = [&](int kt, int buf) {
        for (int i = tid; i < 67 * 16; i += 384) {
            int rr = i >> 4, ch = i & 15;
            u32 dst = sbase + FX(buf) + rr * 256 + ch * 16;
            if (seqstart && rr < 3) {
                *(uint4*)(dsm + FX(buf) + rr * 256 + ch * 16) = make_uint4(0, 0, 0, 0);
            } else {
                CPA16(dst, x + (size_t)(m0 - 3 + rr) * DD + kt * 64 + ch * 4);
            }
        }
        for (int i = tid; i < 64 * 16; i += 384) {
            int r = i >> 4, ch = i & 15;
            size_t gb = (size_t)(kt * 64 + r) * 256 + ch * 16;
            u32 sw = (u32)(ch >> 3) * 8192 + SW128(r * 128 + (ch & 7) * 16);
            CPA16(sbase + FBPH(buf) + sw, (const char*)g_WpH + gb);
            CPA16(sbase + FBPL(buf) + sw, (const char*)g_WpL + gb);
        }
        for (int i = tid; i < 64 * 8; i += 384) {
            int r = i >> 3, ch = i & 7;
            size_t gb = (size_t)(kt * 64 + r) * 128 + ch * 16;
            u32 sw = SW128(r * 128 + ch * 16);
            CPA16(sbase + FBSH(buf) + sw, (const char*)g_WsH + gb);
            CPA16(sbase + FBSL(buf) + sw, (const char*)g_WsL + gb);
        }
    };

    stage(0, 0);
    CPA_COMMIT();

    for (int kt = 0; kt < DD / 64; ++kt) {
        const int buf = kt & 1;
        if (kt + 1 < DD / 64) {
            stage(kt + 1, buf ^ 1);
            CPA_COMMIT();
            CPA_WAIT1();
        } else {
            CPA_WAIT0();
        }
        __syncthreads();

        // ---- conv + split -> sAc(buf); raw x split -> sAx(buf) ----
        char* sX = dsm + FX(buf);
#pragma unroll
        for (int i = tid; i < 64 * 16; i += 384) {
            int r = i >> 4, ch = i & 15;
            float4 xm3 = *(const float4*)(sX + (r + 0) * 256 + ch * 16);
            float4 xm2 = *(const float4*)(sX + (r + 1) * 256 + ch * 16);
            float4 xm1 = *(const float4*)(sX + (r + 2) * 256 + ch * 16);
            float4 xc  = *(const float4*)(sX + (r + 3) * 256 + ch * 16);
            int dcol = kt * 64 + ch * 4;
            float4 w0 = *(const float4*)(cw + 0 * DD + dcol);
            float4 w1 = *(const float4*)(cw + 1 * DD + dcol);
            float4 w2 = *(const float4*)(cw + 2 * DD + dcol);
            float4 w3 = *(const float4*)(cw + 3 * DD + dcol);
            float4 o = make_float4(0.f, 0.f, 0.f, 0.f);
            o = f4fma(o, w0, xm3); o = f4fma(o, w1, xm2);
            o = f4fma(o, w2, xm1); o = f4fma(o, w3, xc);
            u32 sw = SW128(r * 128 + ch * 8);
            split_store8(dsm + FACH(buf) + sw, dsm + FACL(buf) + sw, o);
            split_store8(dsm + FAXH(buf) + sw, dsm + FAXL(buf) + sw, xc);
        }
        __syncthreads();

        // ---- MMA ----
        const u32 aH = sbase + (is_gate ? FACH(buf) : FAXH(buf));
        const u32 aL = sbase + (is_gate ? FACL(buf) : FAXL(buf));
        const u32 bH = sbase + (is_gate ? FBPH(buf) : FBSH(buf));
        const u32 bL = sbase + (is_gate ? FBPL(buf) : FBSL(buf));
#pragma unroll
        for (int ks = 0; ks < 4; ++ks) {
            u32 ah[2][4], al[2][4], bh[4][2], bl[4][2];
#pragma unroll
            for (int mt = 0; mt < 2; ++mt) {
                u32 off = SW128((mw + mt * 16 + arow) * 128 + (ks * 16 + acol) * 2);
                LDSM4(ah[mt], aH + off);
                LDSM4(al[mt], aL + off);
            }
#pragma unroll
            for (int nt = 0; nt < 4; ++nt) {
                int col = nw + nt * 8;
                u32 off = (u32)(col >> 6) * 8192 +
                          SW128((ks * 16 + brow) * 128 + (col & 63) * 2);
                LDSM2T(bh[nt], bH + off);
                LDSM2T(bl[nt], bL + off);
            }
#pragma unroll
            for (int mt = 0; mt < 2; ++mt)
#pragma unroll
                for (int nt = 0; nt < 4; ++nt) {
                    MMA(acc[mt][nt], ah[mt], bh[nt]);
                    MMA(acc[mt][nt], ah[mt], bl[nt]);
                    MMA(acc[mt][nt], al[mt], bh[nt]);
                }
        }
        // REQUIRED: next iteration's stage() overwrites buffers read above.
        __syncthreads();
    }

    // ---- epilogue: u warps -> smem exchange; gate warps -> P and Ct ----
    float* sU = (float*)dsm;   // 64 x USTRIDE floats (reuses FX region, post-barrier)
    if (!is_gate) {
#pragma unroll
        for (int mt = 0; mt < 2; ++mt)
#pragma unroll
            for (int nt = 0; nt < 4; ++nt) {
                int r = mw + mt * 16 + (lane >> 2);
                int col = nw + nt * 8 + 2 * (lane & 3);
                float b0v = ebias[2 * NN + col], b1v = ebias[2 * NN + col + 1];
                sU[r * USTRIDE + col]           = acc[mt][nt][0] + b0v;
                sU[r * USTRIDE + col + 1]       = acc[mt][nt][1] + b1v;
                sU[(r + 8) * USTRIDE + col]     = acc[mt][nt][2] + b0v;
                sU[(r + 8) * USTRIDE + col + 1] = acc[mt][nt][3] + b1v;
            }
    }
    __syncthreads();
    if (is_gate) {
#pragma unroll
        for (int mt = 0; mt < 2; ++mt)
#pragma unroll
            for (int nt = 0; nt < 4; ++nt) {
                int r = mw + mt * 16 + (lane >> 2);
                int col = nw + nt * 8 + 2 * (lane & 3);
                float b0v = ebias[col], b1v = ebias[col + 1];
                float vx = acc[mt][nt][0] + b0v, vy = acc[mt][nt][1] + b1v;
                float vz = acc[mt][nt][2] + b0v, vw = acc[mt][nt][3] + b1v;
                if (col < 64) {
                    float dt0 = sd[col], dt1 = sd[col + 1];
                    float p0 = dt0 * sp(vx) * sU[r * USTRIDE + col];
                    float p1 = dt1 * sp(vy) * sU[r * USTRIDE + col + 1];
                    float p2 = dt0 * sp(vz) * sU[(r + 8) * USTRIDE + col];
                    float p3 = dt1 * sp(vw) * sU[(r + 8) * USTRIDE + col + 1];
                    *(float2*)&g_P[(size_t)(m0 + r) * NN + col] = make_float2(p0, p1);
                    *(float2*)&g_P[(size_t)(m0 + r + 8) * NN + col] = make_float2(p2, p3);
                } else {
                    vx = tanhf(vx); vy = tanhf(vy); vz = tanhf(vz); vw = tanhf(vw);
                    *(float2*)&g_Ct[(size_t)(m0 + r) * NN + col - 64] = make_float2(vx, vy);
                    *(float2*)&g_Ct[(size_t)(m0 + r + 8) * NN + col - 64] = make_float2(vz, vw);
                }
            }
    }
}

// ---------------- kernel 2: out = y @ Wo + bo (N-tile 128, K=64) -----------------
__global__ void __launch_bounds__(256) tc_out(
    const float* __restrict__ bo, float* __restrict__ out)
{
    __shared__ __align__(1024) char sAh[8192], sAl[8192], sBh[16384], sBl[16384];
    const int tid = threadIdx.x;
    const int lane = tid & 31, w = tid >> 5;
    const int mw = (w >> 2) * 32, nw = (w & 3) * 32;
    const int m0 = blockIdx.x * 64;
    const int n0 = blockIdx.y * 128;

    const u32 aAh = s2u(sAh), aAl = s2u(sAl), aBh = s2u(sBh), aBl = s2u(sBl);

#pragma unroll
    for (int i = tid; i < 64 * 8; i += 256) {
        int r = i >> 3, ch = i & 7;
        size_t gb = (size_t)(m0 + r) * 128 + ch * 16;
        u32 sw = SW128(r * 128 + ch * 16);
        CPA16(aAh + sw, (const char*)g_yH + gb);
        CPA16(aAl + sw, (const char*)g_yL + gb);
    }
#pragma unroll
    for (int i = tid; i < 64 * 16; i += 256) {
        int r = i >> 4, ch = i & 15;
        size_t gb = (size_t)r * 2048 + (size_t)n0 * 2 + ch * 16;
        u32 sw = (u32)(ch >> 3) * 8192 + SW128(r * 128 + (ch & 7) * 16);
        CPA16(aBh + sw, (const char*)g_WoH + gb);
        CPA16(aBl + sw, (const char*)g_WoL + gb);
    }
    CPA_COMMIT();
    CPA_WAIT0();
    __syncthreads();

    float acc[2][4][4];
#pragma unroll
    for (int mt = 0; mt < 2; ++mt)
#pragma unroll
        for (int nt = 0; nt < 4; ++nt)
#pragma unroll
            for (int q = 0; q < 4; ++q) acc[mt][nt][q] = 0.f;

    const int arow = lane & 15, acol = (lane >> 4) * 8;
    const int brow = lane & 15;

#pragma unroll
    for (int ks = 0; ks < 4; ++ks) {
        u32 ah[2][4], al[2][4], bh[4][2], bl[4][2];
#pragma unroll
        for (int mt = 0; mt < 2; ++mt) {
            u32 off = SW128((mw + mt * 16 + arow) * 128 + (ks * 16 + acol) * 2);
            LDSM4(ah[mt], aAh + off);
            LDSM4(al[mt], aAl + off);
        }
#pragma unroll
        for (int nt = 0; nt < 4; ++nt) {
            int col = nw + nt * 8;
            u32 off = (u32)(col >> 6) * 8192 +
                      SW128((ks * 16 + brow) * 128 + (col & 63) * 2);
            LDSM2T(bh[nt], aBh + off);
            LDSM2T(bl[nt], aBl + off);
        }
#pragma unroll
        for (int mt = 0; mt < 2; ++mt)
#pragma unroll
            for (int nt = 0; nt < 4; ++nt) {
                MMA(acc[mt][nt], ah[mt], bh[nt]);
                MMA(acc[mt][nt], ah[mt], bl[nt]);
                MMA(acc[mt][nt], al[mt], bh[nt]);
            }
    }

#pragma unroll
    for (int mt = 0; mt < 2; ++mt)
#pragma unroll
        for (int nt = 0; nt < 4; ++nt) {
            int r0 = m0 + mw + mt * 16 + (lane >> 2);
            int col = n0 + nw + nt * 8 + 2 * (lane & 3);
            float b0v = bo[col], b1v = bo[col + 1];
            *(float2*)&out[(size_t)r0 * DD + col] =
                make_float2(acc[mt][nt][0] + b0v, acc[mt][nt][1] + b1v);
            *(float2*)&out[(size_t)(r0 + 8) * DD + col] =
                make_float2(acc[mt][nt][2] + b0v, acc[mt][nt][3] + b1v);
        }
}

// ---------------- scan kernels (chunk-parallel linear recurrence) ----------------
__global__ void __launch_bounds__(256) scan_partial(
    const float* __restrict__ P, const float* __restrict__ sd,
    float* __restrict__ carryT)
{
    const int n = threadIdx.x & 63;
    const int ch = blockIdx.x * 4 + (threadIdx.x >> 6);
    const int b = blockIdx.y;
    const float decay = sd[NN + n];
    const float* p = P + ((size_t)b * LL + (size_t)ch * TCH) * NN + n;
    float s = 0.f;
#pragma unroll
    for (int t = 0; t < TCH; ++t) s = fmaf(decay, s, p[(size_t)t * NN]);
    carryT[((size_t)b * NN + n) * NCH + ch] = s;
}

// warp-parallel carry combine: one warp per (b,n) row of 128 partials.
// Linear recurrence s_i = dp*s_{i-1} + e_i via Kogge-Stone with factor squaring.
// In-place: carryT row becomes the EXCLUSIVE carry-in per chunk.
__global__ void __launch_bounds__(256) scan_carry(
    const float* __restrict__ sd, float* __restrict__ carryT)
{
    const int wid = threadIdx.x >> 5, lane = threadIdx.x & 31;
    const int row = blockIdx.x * 8 + wid;          // 0..255 = b*NN + n
    const int n = row & (NN - 1);
    const float dp = sd[2 * NN + n];

    float4* p = (float4*)(carryT + (size_t)row * NCH) + lane;
    float4 e = *p;

    // local inclusive scan over 4 elements (zero incoming)
    float l0 = e.x;
    float l1 = fmaf(dp, l0, e.y);
    float l2 = fmaf(dp, l1, e.z);
    float l3 = fmaf(dp, l2, e.w);

    // warp inclusive scan over segment totals l3, factor dp^4 (squares per step)
    const float dp2 = dp * dp, dp3 = dp2 * dp, dp4 = dp2 * dp2;
    float s = l3, f = dp4;
#pragma unroll
    for (int k = 1; k < 32; k <<= 1) {
        float t = __shfl_up_sync(0xffffffffu, s, k);
        if (lane >= k) s = fmaf(f, t, s);
        f = f * f;
    }
    float prev = __shfl_up_sync(0xffffffffu, s, 1);   // exclusive segment carry
    if (lane == 0) prev = 0.f;

    // exclusive per-element carries: c_j = dp^j * prev + l_{j-1}
    float4 o;
    o.x = prev;
    o.y = fmaf(dp,  prev, l0);
    o.z = fmaf(dp2, prev, l1);
    o.w = fmaf(dp3, prev, l2);
    *p = o;
}

__global__ void __launch_bounds__(256) scan_final(
    const float* __restrict__ P, const float* __restrict__ Ct,
    const float* __restrict__ sd, const float* __restrict__ carryT)
{
    const int n = threadIdx.x & 63;
    const int ch = blockIdx.x * 4 + (threadIdx.x >> 6);
    const int b = blockIdx.y;
    const float decay = sd[NN + n];
    size_t base = ((size_t)b * LL + (size_t)ch * TCH) * NN + n;
    float s = carryT[((size_t)b * NN + n) * NCH + ch];
#pragma unroll
    for (int t = 0; t < TCH; ++t) {
        size_t idx = base + (size_t)t * NN;
        s = fmaf(decay, s, P[idx]);
        float yv = Ct[idx] * s;
        split1(yv, g_yH[idx], g_yL[idx]);
    }
}

// ---------------- launch ----------------
extern "C" void kernel_launch(void* const* d_in, const int* in_sizes, int n_in,
                              void* d_out, int out_size)
{
    const float* x      = (const float*)d_in[0];
    const float* conv_w = (const float*)d_in[1];
    const float* conv_b = (const float*)d_in[2];
    const float* Wp     = (const float*)d_in[3];
    const float* bp     = (const float*)d_in[4];
    const float* Ws     = (const float*)d_in[5];
    const float* bs     = (const float*)d_in[6];
    const float* A_log  = (const float*)d_in[7];
    const float* dt_log = (const float*)d_in[8];
    const float* Wo     = (const float*)d_in[9];
    const float* bo     = (const float*)d_in[10];
    float* out = (float*)d_out;

    float *p_p, *ct_p, *carry_p, *ebias_p, *sd_p;
    cudaGetSymbolAddress((void**)&p_p,     g_P);
    cudaGetSymbolAddress((void**)&ct_p,    g_Ct);
    cudaGetSymbolAddress((void**)&carry_p, g_carryT);
    cudaGetSymbolAddress((void**)&ebias_p, g_ebias);
    cudaGetSymbolAddress((void**)&sd_p,    g_sd);

    static int attr_done = 0;
    if (!attr_done) {
        cudaFuncSetAttribute(tc_fused, cudaFuncAttributeMaxDynamicSharedMemorySize, FUSED_SMEM);
        attr_done = 1;
    }

    // 0) weights -> bf16 hi/lo, effective biases, scan constants
    prep_kernel<<<64, 256>>>(Wp, Ws, Wo, conv_b, bp, bs, A_log, dt_log, ebias_p, sd_p);

    // 1) fused conv + gate GEMM + u GEMM -> P (= dt*Bt*u) and Ct
    tc_fused<<<MM / 64, 384, FUSED_SMEM>>>(x, conv_w, ebias_p, sd_p);

    // 2) chunk-parallel scan -> y (bf16 hi/lo)
    scan_partial<<<dim3(NCH / 4, BB), 256>>>(p_p, sd_p, carry_p);
    scan_carry<<<32, 256>>>(sd_p, carry_p);
    scan_final<<<dim3(NCH / 4, BB), 256>>>(p_p, ct_p, sd_p, carry_p);

    // 3) out = y @ Wo + bo
    tc_out<<<dim3(MM / 64, DD / 128), 256>>>(bo, out);
}

// round 13
// speedup vs baseline: 1.1130x; 1.0031x over previous
#include <cuda_runtime.h>
#include <cuda_bf16.h>
#include <math.h>
#include <stdint.h>

// Problem dims (fixed by the dataset)
#define BB 4
#define LL 4096
#define DD 1024
#define NN 64
#define MM (BB * LL)
#define NCH 512
#define TCH (LL / NCH)    // 8

typedef unsigned int u32;
typedef __nv_bfloat16 bf16;

// ---------------- scratch (device globals: no allocation allowed) ----------------
__device__ bf16 g_WpH[DD * 2 * NN], g_WpL[DD * 2 * NN];   // [1024][128]
__device__ bf16 g_WsH[DD * NN],     g_WsL[DD * NN];       // [1024][64]
__device__ bf16 g_WoH[NN * DD],     g_WoL[NN * DD];       // [64][1024]
__device__ float g_P [MM * NN];                            // dt * Bt * u
__device__ float g_Ct[MM * NN];
__device__ bf16  g_yH[MM * NN], g_yL[MM * NN];            // [16384][64]
__device__ float g_carryT[BB * NN * NCH];                 // transposed partials
__device__ float g_ebias[3 * NN];
__device__ float g_sd[3 * NN];                            // dt | decay | decay^TCH

// ---------------- helpers ----------------
#define SW128(o) ((u32)(o) ^ ((((u32)(o)) >> 3) & 0x70))

__device__ __forceinline__ u32 s2u(const void* p) {
    u32 a;
    asm("{ .reg .u64 t; cvta.to.shared.u64 t, %1; cvt.u32.u64 %0, t; }" : "=r"(a) : "l"(p));
    return a;
}
__device__ __forceinline__ float sp(float v) { return v > 20.f ? v : log1pf(expf(v)); }

#define LDSM4(r, a)                                                                    \
    asm volatile("ldmatrix.sync.aligned.m8n8.x4.shared.b16 {%0,%1,%2,%3}, [%4];"      \
                 : "=r"((r)[0]), "=r"((r)[1]), "=r"((r)[2]), "=r"((r)[3]) : "r"(a))
#define LDSM2T(r, a)                                                                   \
    asm volatile("ldmatrix.sync.aligned.m8n8.x2.trans.shared.b16 {%0,%1}, [%2];"      \
                 : "=r"((r)[0]), "=r"((r)[1]) : "r"(a))
#define MMA(d, a, b)                                                                   \
    asm volatile("mma.sync.aligned.m16n8k16.row.col.f32.bf16.bf16.f32 "               \
                 "{%0,%1,%2,%3}, {%4,%5,%6,%7}, {%8,%9}, {%0,%1,%2,%3};"              \
                 : "+f"((d)[0]), "+f"((d)[1]), "+f"((d)[2]), "+f"((d)[3])             \
                 : "r"((a)[0]), "r"((a)[1]), "r"((a)[2]), "r"((a)[3]),                \
                   "r"((b)[0]), "r"((b)[1]))

#define CPA16(sa, gp)                                                                  \
    asm volatile("cp.async.cg.shared.global [%0], [%1], 16;" :: "r"((u32)(sa)), "l"(gp))
#define CPA_COMMIT() asm volatile("cp.async.commit_group;" ::: "memory")
#define CPA_WAIT1()  asm volatile("cp.async.wait_group 1;" ::: "memory")
#define CPA_WAIT0()  asm volatile("cp.async.wait_group 0;" ::: "memory")

__device__ __forceinline__ void split1(float v, bf16& h, bf16& l) {
    h = __float2bfloat16(v);
    l = __float2bfloat16(v - __bfloat162float(h));
}
__device__ __forceinline__ void split_store8(char* hiP, char* loP, float4 v) {
    bf16 h0, l0, h1, l1, h2, l2, h3, l3;
    split1(v.x, h0, l0); split1(v.y, h1, l1);
    split1(v.z, h2, l2); split1(v.w, h3, l3);
    __nv_bfloat162 hp0 = {h0, h1}, hp1 = {h2, h3};
    __nv_bfloat162 lp0 = {l0, l1}, lp1 = {l2, l3};
    *(uint2*)hiP = make_uint2(*(u32*)&hp0, *(u32*)&hp1);
    *(uint2*)loP = make_uint2(*(u32*)&lp0, *(u32*)&lp1);
}
__device__ __forceinline__ float4 f4fma(float4 acc, float4 a, float4 b) {
    acc.x = fmaf(a.x, b.x, acc.x); acc.y = fmaf(a.y, b.y, acc.y);
    acc.z = fmaf(a.z, b.z, acc.z); acc.w = fmaf(a.w, b.w, acc.w);
    return acc;
}

// ---------------- kernel 0: weight bf16 hi/lo split + ebias + scan consts --------
__global__ void __launch_bounds__(256) prep_kernel(
    const float* __restrict__ Wp, const float* __restrict__ Ws,
    const float* __restrict__ Wo, const float* __restrict__ cb,
    const float* __restrict__ bp, const float* __restrict__ bs,
    const float* __restrict__ A_log, const float* __restrict__ dt_log,
    float* __restrict__ ebias, float* __restrict__ sd)
{
    const int gtid = blockIdx.x * 256 + threadIdx.x;
    const int NT = gridDim.x * 256;

    for (int i = gtid; i < DD * 2 * NN; i += NT) split1(Wp[i], g_WpH[i], g_WpL[i]);
    for (int i = gtid; i < DD * NN;     i += NT) split1(Ws[i], g_WsH[i], g_WsL[i]);
    for (int i = gtid; i < NN * DD;     i += NT) split1(Wo[i], g_WoH[i], g_WoL[i]);

    if (gtid < 2 * NN) {
        float s = bp[gtid];
#pragma unroll 8
        for (int d = 0; d < DD; ++d) s = fmaf(cb[d], Wp[(size_t)d * 2 * NN + gtid], s);
        ebias[gtid] = s;
    } else if (gtid < 3 * NN) {
        ebias[gtid] = bs[gtid - 2 * NN];
    } else if (gtid < 3 * NN + NN) {
        int n = gtid - 3 * NN;
        float dt = sp(dt_log[n]);
        float decay = 1.f - dt * sp(A_log[n]);
        float dp = decay;
#pragma unroll
        for (int i = 0; i < 3; ++i) dp *= dp;      // decay^8 (TCH = 2^3)
        sd[n] = dt;
        sd[NN + n] = decay;
        sd[2 * NN + n] = dp;
    }
}

// ---------------- kernel 1: fused conv + gates + u, emits P = dt*Bt*u and Ct -----
#define FX(b)   (0      + (b) * 17408)   // raw x: 67 rows x 256B
#define FBPH(b) (34816  + (b) * 16384)   // Wp hi: 64x128 bf16, 2 panels SW128
#define FBPL(b) (67584  + (b) * 16384)
#define FBSH(b) (100352 + (b) * 8192)    // Ws hi: 64x64 bf16 SW128
#define FBSL(b) (116736 + (b) * 8192)
#define FACH(b) (133120 + (b) * 8192)    // conv split hi
#define FACL(b) (149504 + (b) * 8192)
#define FAXH(b) (165888 + (b) * 8192)    // x split hi
#define FAXL(b) (182272 + (b) * 8192)
#define FUSED_SMEM 198656
#define USTRIDE 66                       // u exchange row stride (floats)

__global__ void __launch_bounds__(384, 1) tc_fused(
    const float* __restrict__ x, const float* __restrict__ cw,
    const float* __restrict__ ebias, const float* __restrict__ sd)
{
    extern __shared__ char dsm[];
    const int tid = threadIdx.x;
    const int lane = tid & 31, w = tid >> 5;
    const int m0 = blockIdx.x * 64;
    const bool seqstart = ((m0 & (LL - 1)) == 0);

    const bool is_gate = (w < 8);
    const int mw = is_gate ? ((w >> 2) * 32) : (((w - 8) >> 1) * 32);
    const int nw = is_gate ? ((w & 3) * 32) : (((w - 8) & 1) * 32);

    float acc[2][4][4];
#pragma unroll
    for (int mt = 0; mt < 2; ++mt)
#pragma unroll
        for (int nt = 0; nt < 4; ++nt)
#pragma unroll
            for (int q = 0; q < 4; ++q) acc[mt][nt][q] = 0.f;

    const int arow = lane & 15, acol = (lane >> 4) * 8;
    const int brow = lane & 15;

    const u32 sbase = s2u(dsm);

    auto stage = [&](int kt, int buf) {
        for (int i = tid; i < 67 * 16; i += 384) {
            int rr = i >> 4, ch = i & 15;
            u32 dst = sbase + FX(buf) + rr * 256 + ch * 16;
            if (seqstart && rr < 3) {
                *(uint4*)(dsm + FX(buf) + rr * 256 + ch * 16) = make_uint4(0, 0, 0, 0);
            } else {
                CPA16(dst, x + (size_t)(m0 - 3 + rr) * DD + kt * 64 + ch * 4);
            }
        }
        for (int i = tid; i < 64 * 16; i += 384) {
            int r = i >> 4, ch = i & 15;
            size_t gb = (size_t)(kt * 64 + r) * 256 + ch * 16;
            u32 sw = (u32)(ch >> 3) * 8192 + SW128(r * 128 + (ch & 7) * 16);
            CPA16(sbase + FBPH(buf) + sw, (const char*)g_WpH + gb);
            CPA16(sbase + FBPL(buf) + sw, (const char*)g_WpL + gb);
        }
        for (int i = tid; i < 64 * 8; i += 384) {
            int r = i >> 3, ch = i & 7;
            size_t gb = (size_t)(kt * 64 + r) * 128 + ch * 16;
            u32 sw = SW128(r * 128 + ch * 16);
            CPA16(sbase + FBSH(buf) + sw, (const char*)g_WsH + gb);
            CPA16(sbase + FBSL(buf) + sw, (const char*)g_WsL + gb);
        }
    };

    stage(0, 0);
    CPA_COMMIT();

    for (int kt = 0; kt < DD / 64; ++kt) {
        const int buf = kt & 1;
        if (kt + 1 < DD / 64) {
            stage(kt + 1, buf ^ 1);
            CPA_COMMIT();
            CPA_WAIT1();
        } else {
            CPA_WAIT0();
        }
        __syncthreads();

        // ---- conv + split -> sAc(buf); raw x split -> sAx(buf) ----
        char* sX = dsm + FX(buf);
#pragma unroll
        for (int i = tid; i < 64 * 16; i += 384) {
            int r = i >> 4, ch = i & 15;
            float4 xm3 = *(const float4*)(sX + (r + 0) * 256 + ch * 16);
            float4 xm2 = *(const float4*)(sX + (r + 1) * 256 + ch * 16);
            float4 xm1 = *(const float4*)(sX + (r + 2) * 256 + ch * 16);
            float4 xc  = *(const float4*)(sX + (r + 3) * 256 + ch * 16);
            int dcol = kt * 64 + ch * 4;
            float4 w0 = *(const float4*)(cw + 0 * DD + dcol);
            float4 w1 = *(const float4*)(cw + 1 * DD + dcol);
            float4 w2 = *(const float4*)(cw + 2 * DD + dcol);
            float4 w3 = *(const float4*)(cw + 3 * DD + dcol);
            float4 o = make_float4(0.f, 0.f, 0.f, 0.f);
            o = f4fma(o, w0, xm3); o = f4fma(o, w1, xm2);
            o = f4fma(o, w2, xm1); o = f4fma(o, w3, xc);
            u32 sw = SW128(r * 128 + ch * 8);
            split_store8(dsm + FACH(buf) + sw, dsm + FACL(buf) + sw, o);
            split_store8(dsm + FAXH(buf) + sw, dsm + FAXL(buf) + sw, xc);
        }
        __syncthreads();

        // ---- MMA ----
        const u32 aH = sbase + (is_gate ? FACH(buf) : FAXH(buf));
        const u32 aL = sbase + (is_gate ? FACL(buf) : FAXL(buf));
        const u32 bH = sbase + (is_gate ? FBPH(buf) : FBSH(buf));
        const u32 bL = sbase + (is_gate ? FBPL(buf) : FBSL(buf));
#pragma unroll
        for (int ks = 0; ks < 4; ++ks) {
            u32 ah[2][4], al[2][4], bh[4][2], bl[4][2];
#pragma unroll
            for (int mt = 0; mt < 2; ++mt) {
                u32 off = SW128((mw + mt * 16 + arow) * 128 + (ks * 16 + acol) * 2);
                LDSM4(ah[mt], aH + off);
                LDSM4(al[mt], aL + off);
            }
#pragma unroll
            for (int nt = 0; nt < 4; ++nt) {
                int col = nw + nt * 8;
                u32 off = (u32)(col >> 6) * 8192 +
                          SW128((ks * 16 + brow) * 128 + (col & 63) * 2);
                LDSM2T(bh[nt], bH + off);
                LDSM2T(bl[nt], bL + off);
            }
#pragma unroll
            for (int mt = 0; mt < 2; ++mt)
#pragma unroll
                for (int nt = 0; nt < 4; ++nt) {
                    MMA(acc[mt][nt], ah[mt], bh[nt]);
                    MMA(acc[mt][nt], ah[mt], bl[nt]);
                    MMA(acc[mt][nt], al[mt], bh[nt]);
                }
        }
        // REQUIRED: next iteration's stage() overwrites buffers read above.
        __syncthreads();
    }

    // ---- epilogue: u warps -> smem exchange; gate warps -> P and Ct ----
    float* sU = (float*)dsm;   // 64 x USTRIDE floats (reuses FX region, post-barrier)
    if (!is_gate) {
#pragma unroll
        for (int mt = 0; mt < 2; ++mt)
#pragma unroll
            for (int nt = 0; nt < 4; ++nt) {
                int r = mw + mt * 16 + (lane >> 2);
                int col = nw + nt * 8 + 2 * (lane & 3);
                float b0v = ebias[2 * NN + col], b1v = ebias[2 * NN + col + 1];
                sU[r * USTRIDE + col]           = acc[mt][nt][0] + b0v;
                sU[r * USTRIDE + col + 1]       = acc[mt][nt][1] + b1v;
                sU[(r + 8) * USTRIDE + col]     = acc[mt][nt][2] + b0v;
                sU[(r + 8) * USTRIDE + col + 1] = acc[mt][nt][3] + b1v;
            }
    }
    __syncthreads();
    if (is_gate) {
#pragma unroll
        for (int mt = 0; mt < 2; ++mt)
#pragma unroll
            for (int nt = 0; nt < 4; ++nt) {
                int r = mw + mt * 16 + (lane >> 2);
                int col = nw + nt * 8 + 2 * (lane & 3);
                float b0v = ebias[col], b1v = ebias[col + 1];
                float vx = acc[mt][nt][0] + b0v, vy = acc[mt][nt][1] + b1v;
                float vz = acc[mt][nt][2] + b0v, vw = acc[mt][nt][3] + b1v;
                if (col < 64) {
                    float dt0 = sd[col], dt1 = sd[col + 1];
                    float p0 = dt0 * sp(vx) * sU[r * USTRIDE + col];
                    float p1 = dt1 * sp(vy) * sU[r * USTRIDE + col + 1];
                    float p2 = dt0 * sp(vz) * sU[(r + 8) * USTRIDE + col];
                    float p3 = dt1 * sp(vw) * sU[(r + 8) * USTRIDE + col + 1];
                    *(float2*)&g_P[(size_t)(m0 + r) * NN + col] = make_float2(p0, p1);
                    *(float2*)&g_P[(size_t)(m0 + r + 8) * NN + col] = make_float2(p2, p3);
                } else {
                    vx = tanhf(vx); vy = tanhf(vy); vz = tanhf(vz); vw = tanhf(vw);
                    *(float2*)&g_Ct[(size_t)(m0 + r) * NN + col - 64] = make_float2(vx, vy);
                    *(float2*)&g_Ct[(size_t)(m0 + r + 8) * NN + col - 64] = make_float2(vz, vw);
                }
            }
    }
}

// ---------------- kernel 2: out = y @ Wo + bo (M-tile 128, N-tile 128, K=64) -----
// 8 warps as 4x2 (warp tile 32x64). Staging traffic per block: A 32KB + B 32KB.
#define OAH 0
#define OAL 16384
#define OBH 32768
#define OBL 49152
#define TCOUT_SMEM 65536

__global__ void __launch_bounds__(256) tc_out(
    const float* __restrict__ bo, float* __restrict__ out)
{
    extern __shared__ char dsm[];
    const int tid = threadIdx.x;
    const int lane = tid & 31, w = tid >> 5;
    const int mw = (w >> 1) * 32;        // 4 m-warps
    const int nw = (w & 1) * 64;         // 2 n-warps
    const int m0 = blockIdx.x * 128;
    const int n0 = blockIdx.y * 128;

    const u32 sbase = s2u(dsm);
    const int arow = lane & 15, acol = (lane >> 4) * 8;
    const int brow = lane & 15;

    // stage A: y rows m0..m0+127 (128B rows, hi/lo)
#pragma unroll
    for (int i = tid; i < 128 * 8; i += 256) {
        int r = i >> 3, ch = i & 7;
        size_t gb = (size_t)(m0 + r) * 128 + ch * 16;
        u32 sw = SW128(r * 128 + ch * 16);
        CPA16(sbase + OAH + sw, (const char*)g_yH + gb);
        CPA16(sbase + OAL + sw, (const char*)g_yL + gb);
    }
    // stage B: Wo rows 0..63 (k), cols n0..n0+127 (row bytes 2048), 2 panels
#pragma unroll
    for (int i = tid; i < 64 * 16; i += 256) {
        int r = i >> 4, ch = i & 15;
        size_t gb = (size_t)r * 2048 + (size_t)n0 * 2 + ch * 16;
        u32 sw = (u32)(ch >> 3) * 8192 + SW128(r * 128 + (ch & 7) * 16);
        CPA16(sbase + OBH + sw, (const char*)g_WoH + gb);
        CPA16(sbase + OBL + sw, (const char*)g_WoL + gb);
    }
    CPA_COMMIT();
    CPA_WAIT0();
    __syncthreads();

    float acc[2][8][4];
#pragma unroll
    for (int mt = 0; mt < 2; ++mt)
#pragma unroll
        for (int nt = 0; nt < 8; ++nt)
#pragma unroll
            for (int q = 0; q < 4; ++q) acc[mt][nt][q] = 0.f;

#pragma unroll
    for (int ks = 0; ks < 4; ++ks) {
        u32 ah[2][4], al[2][4], bh[8][2], bl[8][2];
#pragma unroll
        for (int mt = 0; mt < 2; ++mt) {
            u32 off = SW128((mw + mt * 16 + arow) * 128 + (ks * 16 + acol) * 2);
            LDSM4(ah[mt], sbase + OAH + off);
            LDSM4(al[mt], sbase + OAL + off);
        }
#pragma unroll
        for (int nt = 0; nt < 8; ++nt) {
            int col = nw + nt * 8;
            u32 off = (u32)(col >> 6) * 8192 +
                      SW128((ks * 16 + brow) * 128 + (col & 63) * 2);
            LDSM2T(bh[nt], sbase + OBH + off);
            LDSM2T(bl[nt], sbase + OBL + off);
        }
#pragma unroll
        for (int mt = 0; mt < 2; ++mt)
#pragma unroll
            for (int nt = 0; nt < 8; ++nt) {
                MMA(acc[mt][nt], ah[mt], bh[nt]);
                MMA(acc[mt][nt], ah[mt], bl[nt]);
                MMA(acc[mt][nt], al[mt], bh[nt]);
            }
    }

#pragma unroll
    for (int mt = 0; mt < 2; ++mt)
#pragma unroll
        for (int nt = 0; nt < 8; ++nt) {
            int r0 = m0 + mw + mt * 16 + (lane >> 2);
            int col = n0 + nw + nt * 8 + 2 * (lane & 3);
            float b0v = bo[col], b1v = bo[col + 1];
            *(float2*)&out[(size_t)r0 * DD + col] =
                make_float2(acc[mt][nt][0] + b0v, acc[mt][nt][1] + b1v);
            *(float2*)&out[(size_t)(r0 + 8) * DD + col] =
                make_float2(acc[mt][nt][2] + b0v, acc[mt][nt][3] + b1v);
        }
}

// ---------------- scan kernels (chunk-parallel linear recurrence) ----------------
__global__ void __launch_bounds__(256) scan_partial(
    const float* __restrict__ P, const float* __restrict__ sd,
    float* __restrict__ carryT)
{
    const int n = threadIdx.x & 63;
    const int ch = blockIdx.x * 4 + (threadIdx.x >> 6);
    const int b = blockIdx.y;
    const float decay = sd[NN + n];
    const float* p = P + ((size_t)b * LL + (size_t)ch * TCH) * NN + n;
    float s = 0.f;
#pragma unroll
    for (int t = 0; t < TCH; ++t) s = fmaf(decay, s, p[(size_t)t * NN]);
    carryT[((size_t)b * NN + n) * NCH + ch] = s;
}

// warp-parallel carry combine: one warp per (b,n) row of NCH=512 partials.
// Each lane owns 16 consecutive elements; Kogge-Stone warp scan with factor
// squaring combines segment totals. In-place: row becomes EXCLUSIVE carries.
__global__ void __launch_bounds__(256) scan_carry(
    const float* __restrict__ sd, float* __restrict__ carryT)
{
    const int wid = threadIdx.x >> 5, lane = threadIdx.x & 31;
    const int row = blockIdx.x * 8 + wid;          // 0..255 = b*NN + n
    const int n = row & (NN - 1);
    const float dp = sd[2 * NN + n];

    float4* p = (float4*)(carryT + (size_t)row * NCH) + lane * 4;
    float4 e0 = p[0], e1 = p[1], e2 = p[2], e3 = p[3];

    // local inclusive scan over 16 elements
    float l[16];
    l[0]  = e0.x;
    l[1]  = fmaf(dp, l[0],  e0.y);
    l[2]  = fmaf(dp, l[1],  e0.z);
    l[3]  = fmaf(dp, l[2],  e0.w);
    l[4]  = fmaf(dp, l[3],  e1.x);
    l[5]  = fmaf(dp, l[4],  e1.y);
    l[6]  = fmaf(dp, l[5],  e1.z);
    l[7]  = fmaf(dp, l[6],  e1.w);
    l[8]  = fmaf(dp, l[7],  e2.x);
    l[9]  = fmaf(dp, l[8],  e2.y);
    l[10] = fmaf(dp, l[9],  e2.z);
    l[11] = fmaf(dp, l[10], e2.w);
    l[12] = fmaf(dp, l[11], e3.x);
    l[13] = fmaf(dp, l[12], e3.y);
    l[14] = fmaf(dp, l[13], e3.z);
    l[15] = fmaf(dp, l[14], e3.w);

    // warp inclusive scan over segment totals, factor dp^16 (squares per step)
    const float dp2 = dp * dp, dp4 = dp2 * dp2, dp8 = dp4 * dp4, dp16 = dp8 * dp8;
    float s = l[15], f = dp16;
#pragma unroll
    for (int k = 1; k < 32; k <<= 1) {
        float t = __shfl_up_sync(0xffffffffu, s, k);
        if (lane >= k) s = fmaf(f, t, s);
        f = f * f;
    }
    float prev = __shfl_up_sync(0xffffffffu, s, 1);   // exclusive segment carry
    if (lane == 0) prev = 0.f;

    // exclusive per-element carries: c_j = dp^j * prev + l_{j-1}
    float c[16];
    c[0] = prev;
    float dpj = dp;
#pragma unroll
    for (int j = 1; j < 16; ++j) {
        c[j] = fmaf(dpj, prev, l[j - 1]);
        dpj *= dp;
    }
    p[0] = make_float4(c[0],  c[1],  c[2],  c[3]);
    p[1] = make_float4(c[4],  c[5],  c[6],  c[7]);
    p[2] = make_float4(c[8],  c[9],  c[10], c[11]);
    p[3] = make_float4(c[12], c[13], c[14], c[15]);
}

__global__ void __launch_bounds__(256) scan_final(
    const float* __restrict__ P, const float* __restrict__ Ct,
    const float* __restrict__ sd, const float* __restrict__ carryT)
{
    const int n = threadIdx.x & 63;
    const int ch = blockIdx.x * 4 + (threadIdx.x >> 6);
    const int b = blockIdx.y;
    const float decay = sd[NN + n];
    size_t base = ((size_t)b * LL + (size_t)ch * TCH) * NN + n;
    float s = carryT[((size_t)b * NN + n) * NCH + ch];
#pragma unroll
    for (int t = 0; t < TCH; ++t) {
        size_t idx = base + (size_t)t * NN;
        s = fmaf(decay, s, P[idx]);
        float yv = Ct[idx] * s;
        split1(yv, g_yH[idx], g_yL[idx]);
    }
}

// ---------------- launch ----------------
extern "C" void kernel_launch(void* const* d_in, const int* in_sizes, int n_in,
                              void* d_out, int out_size)
{
    const float* x      = (const float*)d_in[0];
    const float* conv_w = (const float*)d_in[1];
    const float* conv_b = (const float*)d_in[2];
    const float* Wp     = (const float*)d_in[3];
    const float* bp     = (const float*)d_in[4];
    const float* Ws     = (const float*)d_in[5];
    const float* bs     = (const float*)d_in[6];
    const float* A_log  = (const float*)d_in[7];
    const float* dt_log = (const float*)d_in[8];
    const float* Wo     = (const float*)d_in[9];
    const float* bo     = (const float*)d_in[10];
    float* out = (float*)d_out;

    float *p_p, *ct_p, *carry_p, *ebias_p, *sd_p;
    cudaGetSymbolAddress((void**)&p_p,     g_P);
    cudaGetSymbolAddress((void**)&ct_p,    g_Ct);
    cudaGetSymbolAddress((void**)&carry_p, g_carryT);
    cudaGetSymbolAddress((void**)&ebias_p, g_ebias);
    cudaGetSymbolAddress((void**)&sd_p,    g_sd);

    static int attr_done = 0;
    if (!attr_done) {
        cudaFuncSetAttribute(tc_fused, cudaFuncAttributeMaxDynamicSharedMemorySize, FUSED_SMEM);
        cudaFuncSetAttribute(tc_out, cudaFuncAttributeMaxDynamicSharedMemorySize, TCOUT_SMEM);
        attr_done = 1;
    }

    // 0) weights -> bf16 hi/lo, effective biases, scan constants
    prep_kernel<<<64, 256>>>(Wp, Ws, Wo, conv_b, bp, bs, A_log, dt_log, ebias_p, sd_p);

    // 1) fused conv + gate GEMM + u GEMM -> P (= dt*Bt*u) and Ct
    tc_fused<<<MM / 64, 384, FUSED_SMEM>>>(x, conv_w, ebias_p, sd_p);

    // 2) chunk-parallel scan -> y (bf16 hi/lo)
    scan_partial<<<dim3(NCH / 4, BB), 256>>>(p_p, sd_p, carry_p);
    scan_carry<<<32, 256>>>(sd_p, carry_p);
    scan_final<<<dim3(NCH / 4, BB), 256>>>(p_p, ct_p, sd_p, carry_p);

    // 3) out = y @ Wo + bo (M-tile 128, N-tile 128)
    tc_out<<<dim3(MM / 128, DD / 128), 256, TCOUT_SMEM>>>(bo, out);
}